// round 1
// baseline (speedup 1.0000x reference)
#include <cuda_runtime.h>

#define T_SAMPLES 8388608
#define NFFT 512
#define HOP 128
#define PAD 256
#define NFRAMES 65537   // 1 + (T + 2*PAD - NFFT)/HOP
#define K_BINS 257
#define SEG 512
#define NSEG 129        // ceil(NFRAMES / SEG)
#define DECAY 0.999f
#define PI_D 3.14159265358979323846

// ---------------- scratch (static device arrays; no allocation) ----------------
__device__ float2 g_spec[(size_t)NFRAMES * K_BINS];     // ~135 MB
__device__ float  g_yframes[(size_t)NFRAMES * NFFT];    // ~134 MB
__device__ float  g_segend[NSEG * K_BINS];
__device__ float  g_prefix[NSEG * K_BINS];
__device__ float2 g_W512[512];
__device__ float  g_win[NFFT];

__device__ __forceinline__ float2 cmul(float2 a, float2 b) {
    return make_float2(a.x * b.x - a.y * b.y, a.x * b.y + a.y * b.x);
}

// ---------------- tables (recomputed every launch; deterministic) ----------------
__global__ void init_tables() {
    int i = threadIdx.x;  // 512 threads
    double ang = -2.0 * PI_D * (double)i / 512.0;
    g_W512[i] = make_float2((float)cos(ang), (float)sin(ang));
    g_win[i]  = (float)(0.5 * (1.0 - cos(2.0 * PI_D * (double)i / 512.0)));
}

// ---------------- 256-pt complex FFT, Stockham radix-2, 128 threads ----------------
// in/out: two 256-entry smem buffers; returns pointer holding the result.
__device__ __forceinline__ float2* fft256(float2* A, float2* B, int t) {
    float2 *in = A, *out = B;
#pragma unroll
    for (int s = 0; s < 8; s++) {
        int Ns = 1 << s;
        int k = t & (Ns - 1);
        int grp = t >> s;
        float2 w = g_W512[k << (8 - s)];      // exp(-2*pi*i*k/(2*Ns))
        float2 a = in[t];
        float2 b = in[t + 128];
        float2 tb = cmul(w, b);
        int o = (grp << (s + 1)) + k;
        out[o]      = make_float2(a.x + tb.x, a.y + tb.y);
        out[o + Ns] = make_float2(a.x - tb.x, a.y - tb.y);
        __syncthreads();
        float2* tmp = in; in = out; out = tmp;
    }
    return in;
}

// ---------------- forward: frame -> windowed -> rfft(512) ----------------
__global__ __launch_bounds__(128) void fwd_fft(const float* __restrict__ x) {
    __shared__ float2 bufA[256], bufB[256];
    int f = blockIdx.x, t = threadIdx.x;

    // load 512 samples with reflect pad + window; float view of bufA packs
    // z[k] = xw[2k] + i*xw[2k+1] for free.
    float* sA = (float*)bufA;
#pragma unroll
    for (int n = t; n < NFFT; n += 128) {
        int p = f * HOP + n - PAD;
        if (p < 0) p = -p;
        else if (p >= T_SAMPLES) p = 2 * T_SAMPLES - 2 - p;
        sA[n] = x[p] * g_win[n];
    }
    __syncthreads();

    float2* Z = fft256(bufA, bufB, t);

    // untwiddle packed FFT -> rfft bins X[0..256]
#pragma unroll
    for (int k = t; k < K_BINS; k += 128) {
        int km = (256 - k) & 255;
        float2 zk = Z[k & 255];
        float2 zm = Z[km];
        float2 ze  = make_float2(0.5f * (zk.x + zm.x), 0.5f * (zk.y - zm.y));
        float2 d   = make_float2(0.5f * (zk.x - zm.x), 0.5f * (zk.y + zm.y));
        float2 mid = make_float2(d.y, -d.x);          // -i * d
        float2 w = g_W512[k & 511];                   // k=256 -> W512[256] = -1
        float2 wm = cmul(w, mid);
        g_spec[(size_t)f * K_BINS + k] = make_float2(ze.x + wm.x, ze.y + wm.y);
    }
}

// ---------------- scan pass 1: per-segment running-max summaries ----------------
__global__ __launch_bounds__(288) void scan_seg() {
    int k = threadIdx.x;
    if (k >= K_BINS) return;
    int s = blockIdx.x;
    int j0 = s * SEG;
    int j1 = min(j0 + SEG, NFRAMES);
    float r = 0.0f;
    for (int j = j0; j < j1; j++) {
        float2 c = g_spec[(size_t)j * K_BINS + k];
        float m = sqrtf(c.x * c.x + c.y * c.y);
        r = fmaxf(DECAY * r, m);
    }
    g_segend[s * K_BINS + k] = r;
}

// ---------------- scan pass 2: cross-segment exclusive scan (tiny) ----------------
__global__ __launch_bounds__(288) void scan_combine() {
    int k = threadIdx.x;
    if (k >= K_BINS) return;
    float DP = (float)pow((double)DECAY, (double)SEG);
    float carry = 0.0f;
    for (int s = 0; s < NSEG; s++) {
        g_prefix[s * K_BINS + k] = carry;
        carry = fmaxf(DP * carry, g_segend[s * K_BINS + k]);
    }
}

// ---------------- scan pass 3: apply gain, in-place on spec ----------------
__global__ __launch_bounds__(288) void scan_apply() {
    int k = threadIdx.x;
    if (k >= K_BINS) return;
    int s = blockIdx.x;
    int j0 = s * SEG;
    int j1 = min(j0 + SEG, NFRAMES);
    float r = g_prefix[s * K_BINS + k];
    for (int j = j0; j < j1; j++) {
        size_t idx = (size_t)j * K_BINS + k;
        float2 c = g_spec[idx];
        float m2 = c.x * c.x + c.y * c.y;
        float m = sqrtf(m2);
        r = fmaxf(DECAY * r, m);
        float denom = fmaxf(0.5f * r * r, 1e-8f);   // REVERB_EST = 0.5
        float snr = m2 / denom;
        float g = snr / (1.0f + snr);
        g_spec[idx] = make_float2(g * c.x, g * c.y);
    }
}

// ---------------- inverse: irfft(512) * win -> time frames ----------------
__global__ __launch_bounds__(128) void inv_fft() {
    __shared__ float2 S[K_BINS];
    __shared__ float2 bufA[256], bufB[256];
    int f = blockIdx.x, t = threadIdx.x;

#pragma unroll
    for (int k = t; k < K_BINS; k += 128)
        S[k] = g_spec[(size_t)f * K_BINS + k];
    __syncthreads();

    // re-pack rfft bins into 256-pt complex spectrum; store conj for
    // inverse-via-forward-FFT trick.
#pragma unroll
    for (int k = t; k < 256; k += 128) {
        float2 xk = S[k];
        float2 xm = S[256 - k];
        float2 ze = make_float2(0.5f * (xk.x + xm.x), 0.5f * (xk.y - xm.y));
        float2 d  = make_float2(0.5f * (xk.x - xm.x), 0.5f * (xk.y + xm.y));
        float2 w  = g_W512[k];
        float2 wc = make_float2(w.x, -w.y);          // W^{-k}
        float2 zo = cmul(wc, d);
        // Z = ze + i*zo ; write conj(Z)
        bufA[k] = make_float2(ze.x - zo.y, -(ze.y + zo.x));
    }
    __syncthreads();

    float2* O = fft256(bufA, bufB, t);

    // time samples: z[k] = conj(O[k]) / 256 ; x[2k]=Re, x[2k+1]=Im ; apply window
    const float scale = 1.0f / 256.0f;
#pragma unroll
    for (int k = t; k < 256; k += 128) {
        float2 o = O[k];
        size_t base = (size_t)f * NFFT + 2 * k;
        g_yframes[base]     =  o.x * scale * g_win[2 * k];
        g_yframes[base + 1] = -o.y * scale * g_win[2 * k + 1];
    }
}

// ---------------- overlap-add by gather + win^2 normalize + trim ----------------
__global__ __launch_bounds__(256) void gather_norm(float* __restrict__ out) {
    int i = blockIdx.x * blockDim.x + threadIdx.x;
    if (i >= T_SAMPLES) return;
    int tpos = i + PAD;
    int fmax = tpos >> 7;                  // floor(t/128)
    if (fmax > NFRAMES - 1) fmax = NFRAMES - 1;
    int fmin = (tpos - 384) >> 7;          // ceil((t-511)/128) via floor((t-384)/128)
    if (fmin < 0) fmin = 0;
    float acc = 0.0f, ws = 0.0f;
#pragma unroll 4
    for (int fr = fmin; fr <= fmax; fr++) {
        int n = tpos - (fr << 7);
        float w = g_win[n];
        acc += g_yframes[(size_t)fr * NFFT + n];
        ws += w * w;
    }
    out[i] = acc / fmaxf(ws, 1e-11f);
}

// ---------------- launch ----------------
extern "C" void kernel_launch(void* const* d_in, const int* in_sizes, int n_in,
                              void* d_out, int out_size) {
    const float* x = (const float*)d_in[0];
    float* out = (float*)d_out;

    init_tables<<<1, 512>>>();
    fwd_fft<<<NFRAMES, 128>>>(x);
    scan_seg<<<NSEG, 288>>>();
    scan_combine<<<1, 288>>>();
    scan_apply<<<NSEG, 288>>>();
    inv_fft<<<NFRAMES, 128>>>();
    gather_norm<<<(T_SAMPLES + 255) / 256, 256>>>(out);
}

// round 2
// speedup vs baseline: 2.4425x; 2.4425x over previous
#include <cuda_runtime.h>

#define T_SAMPLES 8388608
#define NFFT 512
#define HOP 128
#define PAD 256
#define NFRAMES 65537   // 1 + (T + 2*PAD - NFFT)/HOP
#define K_BINS 257
#define SEG 512
#define NSEG 129        // ceil(NFRAMES / SEG)
#define DECAYF 0.999f
#define PI_D 3.14159265358979323846

// ---------------- scratch (static device arrays; no allocation) ----------------
__device__ float2 g_spec[(size_t)NFRAMES * K_BINS];     // ~135 MB
__device__ float  g_rloc[(size_t)NFRAMES * K_BINS];     // ~67 MB: within-seg running max
__device__ float  g_yframes[(size_t)NFRAMES * NFFT];    // ~134 MB
__device__ float  g_prefix[NSEG * K_BINS];
__device__ float2 g_W512[512];
__device__ float  g_win[NFFT];
__device__ float  g_Dpow[513];

__device__ __forceinline__ float2 cmul(float2 a, float2 b) {
    return make_float2(a.x * b.x - a.y * b.y, a.x * b.y + a.y * b.x);
}
__device__ __forceinline__ float2 csub(float2 a, float2 b) {
    return make_float2(a.x - b.x, a.y - b.y);
}
__device__ __forceinline__ float2 cadd(float2 a, float2 b) {
    return make_float2(a.x + b.x, a.y + b.y);
}
__device__ __forceinline__ int brev8(int x) { return (int)(__brev((unsigned)x) >> 24); }

// ---------------- tables ----------------
__global__ void init_tables() {
    int i = threadIdx.x;  // 512 threads
    double ang = -2.0 * PI_D * (double)i / 512.0;
    g_W512[i] = make_float2((float)cos(ang), (float)sin(ang));
    g_win[i]  = (float)(0.5 * (1.0 - cos(2.0 * PI_D * (double)i / 512.0)));
    g_Dpow[i] = (float)pow((double)DECAYF, (double)i);
    if (i == 0) g_Dpow[512] = (float)pow((double)DECAYF, 512.0);
}

// ---------------- warp-level 256-pt complex FFT (DIF radix-2) ----------------
// Data layout: register j (0..7), lane l: holds x[32*j + l].
// Output: register j lane l holds X[brev8(32*j + l)].
__device__ __forceinline__ float2 bfly(float2 v, int m, float2 tw, int lane) {
    float2 o;
    o.x = __shfl_xor_sync(0xffffffffu, v.x, m);
    o.y = __shfl_xor_sync(0xffffffffu, v.y, m);
    float2 s = cadd(v, o);
    float2 d = csub(o, v);        // up lane: (a - b)
    float2 dm = cmul(d, tw);
    return (lane & m) ? dm : s;
}

__device__ __forceinline__ void warp_fft256(float2 r[8], int lane, const float2* s_W) {
    // stage h=128 (register pairs j, j+4), twiddle W_256^n = s_W[2n]
#pragma unroll
    for (int j = 0; j < 4; j++) {
        float2 a = r[j], b = r[j + 4];
        float2 w = s_W[2 * (32 * j + lane)];
        r[j] = cadd(a, b);
        r[j + 4] = cmul(csub(a, b), w);
    }
    // stage h=64 (pairs j, j+2 within halves), W_128^m = s_W[4m]
#pragma unroll
    for (int half = 0; half < 2; half++) {
#pragma unroll
        for (int j = 0; j < 2; j++) {
            int lo = half * 4 + j;
            float2 a = r[lo], b = r[lo + 2];
            float2 w = s_W[4 * (32 * j + lane)];
            r[lo] = cadd(a, b);
            r[lo + 2] = cmul(csub(a, b), w);
        }
    }
    // stage h=32 (pairs 2q, 2q+1), W_64^l = s_W[8l]
    {
        float2 w = s_W[8 * lane];
#pragma unroll
        for (int q = 0; q < 4; q++) {
            int lo = 2 * q;
            float2 a = r[lo], b = r[lo + 1];
            r[lo] = cadd(a, b);
            r[lo + 1] = cmul(csub(a, b), w);
        }
    }
    // shuffle stages: h = 16, 8, 4, 2, 1
    {
        float2 tw = s_W[16 * (lane & 15)];
#pragma unroll
        for (int j = 0; j < 8; j++) r[j] = bfly(r[j], 16, tw, lane);
    }
    {
        float2 tw = s_W[32 * (lane & 7)];
#pragma unroll
        for (int j = 0; j < 8; j++) r[j] = bfly(r[j], 8, tw, lane);
    }
    {
        float2 tw = s_W[64 * (lane & 3)];
#pragma unroll
        for (int j = 0; j < 8; j++) r[j] = bfly(r[j], 4, tw, lane);
    }
    {
        float2 tw = (lane & 1) ? make_float2(0.0f, -1.0f) : make_float2(1.0f, 0.0f);
#pragma unroll
        for (int j = 0; j < 8; j++) r[j] = bfly(r[j], 2, tw, lane);
    }
    {
        float2 tw = make_float2(1.0f, 0.0f);
#pragma unroll
        for (int j = 0; j < 8; j++) r[j] = bfly(r[j], 1, tw, lane);
    }
}

// ---------------- forward: frame -> windowed -> rfft(512), 8 frames/block ----------------
__global__ __launch_bounds__(256) void fwd_fft(const float* __restrict__ x) {
    __shared__ float2 s_W[512];
    __shared__ float2 s_win2[256];
    __shared__ float2 s_Z[8][256];
    int t = threadIdx.x, lane = t & 31, w = t >> 5;
#pragma unroll
    for (int i = t; i < 512; i += 256) s_W[i] = g_W512[i];
    s_win2[t] = make_float2(g_win[2 * t], g_win[2 * t + 1]);
    __syncthreads();

    int f = blockIdx.x * 8 + w;
    if (f >= NFRAMES) return;

    float2 r[8];
    int p0 = f * HOP - PAD;
    if (p0 >= 0 && p0 + NFFT <= T_SAMPLES) {
        const float2* xv = (const float2*)(x + p0);
#pragma unroll
        for (int j = 0; j < 8; j++) {
            int k = 32 * j + lane;
            float2 v = xv[k];
            float2 w2 = s_win2[k];
            r[j] = make_float2(v.x * w2.x, v.y * w2.y);
        }
    } else {
#pragma unroll
        for (int j = 0; j < 8; j++) {
            int k = 32 * j + lane;
            int pa = p0 + 2 * k, pb = pa + 1;
            if (pa < 0) pa = -pa; else if (pa >= T_SAMPLES) pa = 2 * T_SAMPLES - 2 - pa;
            if (pb < 0) pb = -pb; else if (pb >= T_SAMPLES) pb = 2 * T_SAMPLES - 2 - pb;
            float2 w2 = s_win2[k];
            r[j] = make_float2(x[pa] * w2.x, x[pb] * w2.y);
        }
    }

    warp_fft256(r, lane, s_W);

    // scatter to natural order (bit-reversal)
#pragma unroll
    for (int j = 0; j < 8; j++)
        s_Z[w][brev8(32 * j + lane)] = r[j];
    __syncwarp();

    // untwiddle packed FFT -> rfft bins X[0..256]
    float2* S = s_Z[w];
    size_t base = (size_t)f * K_BINS;
    for (int k = lane; k < K_BINS; k += 32) {
        int km = (256 - k) & 255;
        float2 zk = S[k & 255];
        float2 zm = S[km];
        float2 ze = make_float2(0.5f * (zk.x + zm.x), 0.5f * (zk.y - zm.y));
        float2 d  = make_float2(0.5f * (zk.x - zm.x), 0.5f * (zk.y + zm.y));
        float2 mid = make_float2(d.y, -d.x);          // -i * d
        float2 tw = s_W[k & 511];
        float2 wm = cmul(tw, mid);
        g_spec[base + k] = make_float2(ze.x + wm.x, ze.y + wm.y);
    }
}

// ---------------- pass 1: within-segment inclusive running max (stores every frame) ----------------
__global__ __launch_bounds__(288) void scan_seg() {
    int k = threadIdx.x;
    if (k >= K_BINS) return;
    int s = blockIdx.x;
    int j0 = s * SEG;
    int j1 = min(j0 + SEG, NFRAMES);
    float r = 0.0f;
    int j = j0;
    for (; j + 16 <= j1; j += 16) {
        float2 c[16];
#pragma unroll
        for (int u = 0; u < 16; u++) c[u] = g_spec[(size_t)(j + u) * K_BINS + k];
#pragma unroll
        for (int u = 0; u < 16; u++) {
            float m = sqrtf(c[u].x * c[u].x + c[u].y * c[u].y);
            r = fmaxf(DECAYF * r, m);
            g_rloc[(size_t)(j + u) * K_BINS + k] = r;
        }
    }
    for (; j < j1; j++) {
        float2 c = g_spec[(size_t)j * K_BINS + k];
        float m = sqrtf(c.x * c.x + c.y * c.y);
        r = fmaxf(DECAYF * r, m);
        g_rloc[(size_t)j * K_BINS + k] = r;
    }
}

// ---------------- pass 2: cross-segment exclusive scan (small, MLP-unrolled) ----------------
__global__ __launch_bounds__(288) void scan_combine() {
    int k = threadIdx.x;
    if (k >= K_BINS) return;
    float DP = g_Dpow[512];
    float carry = 0.0f;
    int s = 0;
    for (; s + 8 <= NSEG; s += 8) {
        float v[8];
#pragma unroll
        for (int u = 0; u < 8; u++) {
            int last = min((s + u + 1) * SEG, NFRAMES) - 1;
            v[u] = g_rloc[(size_t)last * K_BINS + k];
        }
#pragma unroll
        for (int u = 0; u < 8; u++) {
            g_prefix[(s + u) * K_BINS + k] = carry;
            carry = fmaxf(DP * carry, v[u]);
        }
    }
    for (; s < NSEG; s++) {
        int last = min((s + 1) * SEG, NFRAMES) - 1;
        g_prefix[s * K_BINS + k] = carry;
        carry = fmaxf(DP * carry, g_rloc[(size_t)last * K_BINS + k]);
    }
}

// ---------------- inverse: gain (fused) -> irfft(512) * win -> time frames ----------------
__global__ __launch_bounds__(256) void inv_fft() {
    __shared__ float2 s_W[512];
    __shared__ float  s_win[512];
    __shared__ float2 s_S[8][260];   // 257 used, padded
    __shared__ float  s_Y[8][512];
    int t = threadIdx.x, lane = t & 31, w = t >> 5;
#pragma unroll
    for (int i = t; i < 512; i += 256) {
        s_W[i] = g_W512[i];
        s_win[i] = g_win[i];
    }
    __syncthreads();

    int f = blockIdx.x * 8 + w;
    if (f >= NFRAMES) return;

    int seg = f >> 9;
    float dp = g_Dpow[(f - (seg << 9)) + 1];
    size_t base = (size_t)f * K_BINS;
    const float* pref = g_prefix + seg * K_BINS;

    // load bins, apply Wiener gain inline
    for (int k = lane; k < K_BINS; k += 32) {
        float2 c = g_spec[base + k];
        float rl = g_rloc[base + k];
        float rr = fmaxf(dp * pref[k], rl);
        float m2 = c.x * c.x + c.y * c.y;
        float g = m2 / (fmaxf(0.5f * rr * rr, 1e-8f) + m2);
        s_S[w][k] = make_float2(g * c.x, g * c.y);
    }
    __syncwarp();

    // re-pack rfft bins into 256-pt spectrum, conj for inverse-via-forward
    float2 r[8];
#pragma unroll
    for (int j = 0; j < 8; j++) {
        int k = 32 * j + lane;
        float2 xk = s_S[w][k];
        float2 xm = s_S[w][256 - k];
        float2 ze = make_float2(0.5f * (xk.x + xm.x), 0.5f * (xk.y - xm.y));
        float2 d  = make_float2(0.5f * (xk.x - xm.x), 0.5f * (xk.y + xm.y));
        float2 tw = s_W[k];
        float2 wc = make_float2(tw.x, -tw.y);          // W^{-k}
        float2 zo = cmul(wc, d);
        r[j] = make_float2(ze.x - zo.y, -(ze.y + zo.x));   // conj(ze + i*zo)
    }

    warp_fft256(r, lane, s_W);

    // time samples: z[k] = conj(O[k])/256 ; x[2k]=Re, x[2k+1]=Im
#pragma unroll
    for (int j = 0; j < 8; j++) {
        int pos = brev8(32 * j + lane);
        s_Y[w][2 * pos]     = r[j].x;
        s_Y[w][2 * pos + 1] = -r[j].y;
    }
    __syncwarp();

    const float scale = 1.0f / 256.0f;
    size_t ybase = (size_t)f * NFFT;
    for (int m = lane; m < NFFT; m += 32)
        g_yframes[ybase + m] = s_Y[w][m] * s_win[m] * scale;
}

// ---------------- overlap-add by gather + win^2 normalize + trim ----------------
__global__ __launch_bounds__(256) void gather_norm(float* __restrict__ out) {
    int i = blockIdx.x * blockDim.x + threadIdx.x;
    if (i >= T_SAMPLES) return;
    int tpos = i + PAD;
    int fmax = tpos >> 7;
    if (fmax > NFRAMES - 1) fmax = NFRAMES - 1;
    int fmin = (tpos - 384) >> 7;
    if (fmin < 0) fmin = 0;
    float acc = 0.0f, ws = 0.0f;
#pragma unroll 4
    for (int fr = fmin; fr <= fmax; fr++) {
        int n = tpos - (fr << 7);
        float wv = g_win[n];
        acc += g_yframes[(size_t)fr * NFFT + n];
        ws += wv * wv;
    }
    out[i] = acc / fmaxf(ws, 1e-11f);
}

// ---------------- launch ----------------
extern "C" void kernel_launch(void* const* d_in, const int* in_sizes, int n_in,
                              void* d_out, int out_size) {
    const float* x = (const float*)d_in[0];
    float* out = (float*)d_out;

    init_tables<<<1, 512>>>();
    fwd_fft<<<(NFRAMES + 7) / 8, 256>>>(x);
    scan_seg<<<NSEG, 288>>>();
    scan_combine<<<1, 288>>>();
    inv_fft<<<(NFRAMES + 7) / 8, 256>>>();
    gather_norm<<<(T_SAMPLES + 255) / 256, 256>>>(out);
}